// round 10
// baseline (speedup 1.0000x reference)
#include <cuda_runtime.h>
#include <math.h>
#include <stdint.h>

// Problem constants
#define BB   64
#define NN   4096
#define IND  256
#define SS   8
#define DD   256
#define ROWS (BB*SS)        // 512
#define NG   16             // attention groups (blocks.y)
#define TN   32             // n's per tile
#define NTILE 8             // tiles per block (NG*NTILE*TN = 4096)

// -------- scratch (device globals; no allocation allowed) --------
__device__ float g_slots [ROWS*DD];
__device__ float g_qW    [ROWS*IND];
__device__ float g_upart [NG*ROWS*IND];   // unnormalized U partials (8 MB)
__device__ float g_m     [NG*ROWS];
__device__ float g_l     [NG*ROWS];
__device__ float g_wT    [9*DD*DD];       // transposed weights: [m][k][out]

// -------- reductions --------
__device__ __forceinline__ float warpSum(float v){
#pragma unroll
    for (int o = 16; o > 0; o >>= 1) v += __shfl_xor_sync(0xffffffffu, v, o);
    return v;
}
__device__ __forceinline__ float warpMax(float v){
#pragma unroll
    for (int o = 16; o > 0; o >>= 1) v = fmaxf(v, __shfl_xor_sync(0xffffffffu, v, o));
    return v;
}

// -------- slots = mu + sigma * noise --------
__global__ void init_slots_kernel(const float* __restrict__ noise,
                                  const float* __restrict__ mu,
                                  const float* __restrict__ sigma,
                                  float* __restrict__ slots){
    int i  = blockIdx.x * 256 + threadIdx.x;
    int sd = i & (SS*DD - 1);
    slots[i] = mu[sd] + sigma[sd] * noise[i];
}

// -------- one-shot weight transpose: wT[m][k][o] = W_m[o][k] --------
// grid 9*64 blocks (m, 8x8 tiles of 32x32), 256 threads.
__global__ void transpose_kernel(const float* __restrict__ Wv,
                                 const float* __restrict__ W_ih,
                                 const float* __restrict__ W_hh,
                                 const float* __restrict__ W1,
                                 const float* __restrict__ W2,
                                 float* __restrict__ wT)
{
    int m    = blockIdx.x >> 6;
    int tile = blockIdx.x & 63;
    int ob = (tile >> 3) * 32, kb = (tile & 7) * 32;
    const float* src;
    if (m == 0)      src = Wv;
    else if (m < 4)  src = W_ih + (size_t)(m-1)*DD*DD;
    else if (m < 7)  src = W_hh + (size_t)(m-4)*DD*DD;
    else if (m == 7) src = W1;
    else             src = W2;
    __shared__ float tl[32][33];
    int tx = threadIdx.x & 31, ty = threadIdx.x >> 5;
#pragma unroll
    for (int p = 0; p < 4; ++p)
        tl[ty + p*8][tx] = src[(size_t)(ob + ty + p*8)*DD + kb + tx];
    __syncthreads();
    float* dst = wT + (size_t)m*DD*DD;
#pragma unroll
    for (int p = 0; p < 4; ++p)
        dst[(size_t)(kb + ty + p*8)*DD + ob + tx] = tl[tx][ty + p*8];
}

// Block LayerNorm (256-thread data path; callable from 256 OR 512 threads).
__device__ __forceinline__ void block_ln4(const float v[4], float o[4],
                                          const float* __restrict__ g,
                                          const float* __restrict__ b, int t)
{
    __shared__ float part[8][4];
    __shared__ float stat[4];
    int w = t >> 5, l = t & 31;
#pragma unroll
    for (int r = 0; r < 4; ++r){
        float p = warpSum(v[r]);
        if (l == 0 && w < 8) part[w][r] = p;
    }
    __syncthreads();
    if (t < 32){
        int rr = l >> 3, ww = l & 7;
        float x = part[ww][rr];
        x += __shfl_xor_sync(0xffffffffu, x, 1);
        x += __shfl_xor_sync(0xffffffffu, x, 2);
        x += __shfl_xor_sync(0xffffffffu, x, 4);
        if (ww == 0) stat[rr] = x * (1.f/256.f);
    }
    __syncthreads();
    float d[4];
#pragma unroll
    for (int r = 0; r < 4; ++r) d[r] = v[r] - stat[r];
    __syncthreads();
#pragma unroll
    for (int r = 0; r < 4; ++r){
        float p = warpSum(d[r]*d[r]);
        if (l == 0 && w < 8) part[w][r] = p;
    }
    __syncthreads();
    if (t < 32){
        int rr = l >> 3, ww = l & 7;
        float x = part[ww][rr];
        x += __shfl_xor_sync(0xffffffffu, x, 1);
        x += __shfl_xor_sync(0xffffffffu, x, 2);
        x += __shfl_xor_sync(0xffffffffu, x, 4);
        if (ww == 0) stat[rr] = rsqrtf(x * (1.f/256.f) + 1e-5f);
    }
    __syncthreads();
    int tc = t & 255;
    float gg = g[tc], bb = b[tc];
#pragma unroll
    for (int r = 0; r < 4; ++r) o[r] = d[r] * stat[r] * gg + bb;
}

// ============ PRE: LN(slots) -> q=ln@Wq^T+bq -> qW=(q@Wk)*inv_sqrt_d ============
__global__ __launch_bounds__(256) void pre_kernel(
        const float* __restrict__ slots,
        const float* __restrict__ lng, const float* __restrict__ lnb,
        const float* __restrict__ Wq,  const float* __restrict__ bq,
        const float* __restrict__ Wk,
        float* __restrict__ qW)
{
    int r0 = blockIdx.x * 4;
    int t  = threadIdx.x;
    __shared__ float s_ln[4][DD];
    __shared__ float s_q [4][DD];

    float v[4];
#pragma unroll
    for (int r = 0; r < 4; ++r) v[r] = slots[(size_t)(r0+r)*DD + t];
    float o[4];
    block_ln4(v, o, lng, lnb, t);
#pragma unroll
    for (int r = 0; r < 4; ++r) s_ln[r][t] = o[r];
    __syncthreads();

    {   // q[r, n=t] = s_ln[r] . Wq[t,:] + bq[t]
        const float4* wrow = reinterpret_cast<const float4*>(Wq + (size_t)t*DD);
        float a0=0.f, a1=0.f, a2=0.f, a3=0.f;
#pragma unroll 8
        for (int k4 = 0; k4 < 64; ++k4){
            float4 wv = __ldg(&wrow[k4]);
            int k = k4*4;
            a0 += s_ln[0][k]*wv.x + s_ln[0][k+1]*wv.y + s_ln[0][k+2]*wv.z + s_ln[0][k+3]*wv.w;
            a1 += s_ln[1][k]*wv.x + s_ln[1][k+1]*wv.y + s_ln[1][k+2]*wv.z + s_ln[1][k+3]*wv.w;
            a2 += s_ln[2][k]*wv.x + s_ln[2][k+1]*wv.y + s_ln[2][k+2]*wv.z + s_ln[2][k+3]*wv.w;
            a3 += s_ln[3][k]*wv.x + s_ln[3][k+1]*wv.y + s_ln[3][k+2]*wv.z + s_ln[3][k+3]*wv.w;
        }
        float bv = __ldg(&bq[t]);
        s_q[0][t] = a0 + bv; s_q[1][t] = a1 + bv;
        s_q[2][t] = a2 + bv; s_q[3][t] = a3 + bv;
    }
    __syncthreads();

    {   // qW[r, e=t] = (s_q[r] @ Wk[:,t]) / 16
        float c0=0.f, c1=0.f, c2=0.f, c3=0.f;
#pragma unroll 8
        for (int d = 0; d < DD; ++d){
            float wv = __ldg(&Wk[(size_t)d*IND + t]);
            c0 += s_q[0][d]*wv; c1 += s_q[1][d]*wv;
            c2 += s_q[2][d]*wv; c3 += s_q[3][d]*wv;
        }
        qW[(size_t)(r0+0)*IND + t] = c0 * 0.0625f;
        qW[(size_t)(r0+1)*IND + t] = c1 * 0.0625f;
        qW[(size_t)(r0+2)*IND + t] = c2 * 0.0625f;
        qW[(size_t)(r0+3)*IND + t] = c3 * 0.0625f;
    }
}

// ============ FLASH attention, TN=32 tiles, 2 blocks/SM, 3 barriers/tile ============
__global__ __launch_bounds__(512, 2) void attn_kernel(
        const float* __restrict__ qW,
        const float* __restrict__ inputs,
        float* __restrict__ upart,
        float* __restrict__ mbuf,
        float* __restrict__ lbuf)
{
    extern __shared__ float dsm[];
    float* Xs  = dsm;                  // 2 * 8192 floats (64 KB)
    float* qT  = dsm + 16384;          // [k][s] 2048
    float* lgp = qT  + 2048;           // [ks][s][n] 16*8*32 = 4096
    float* atT = lgp + 4096;           // [n][12] 384
    float* scs = atT + 384;            // 8

    int b = blockIdx.x, g = blockIdx.y;
    int t = threadIdx.x, w = t >> 5, l = t & 31;

    // stage qT
#pragma unroll
    for (int p = 0; p < 4; ++p){
        int idx = t + p*512;
        qT[(idx & 255)*8 + (idx >> 8)] = qW[(size_t)b*2048 + idx];
    }

    const float* src0 = inputs + ((size_t)b*NN + g*(NTILE*TN))*IND;
#define PREFETCH(j, buf) do {                                                   \
        const float* _s = src0 + (size_t)(j)*TN*IND;                            \
        float* _d = Xs + (buf)*8192;                                            \
        _Pragma("unroll")                                                       \
        for (int p = 0; p < 4; ++p){                                            \
            int idx = t + p*512;                                                \
            int n = idx >> 6, k4 = idx & 63;                                    \
            uint32_t sa = (uint32_t)__cvta_generic_to_shared(                   \
                              &_d[(n*64 + (k4 ^ (n & 7)))*4]);                  \
            asm volatile("cp.async.cg.shared.global [%0], [%1], 16;"            \
                         :: "r"(sa), "l"(_s + (size_t)n*IND + k4*4) : "memory");\
        }                                                                       \
        asm volatile("cp.async.commit_group;" ::: "memory");                    \
    } while(0)

    PREFETCH(0, 0);

    float m_run = -3.4e38f, lpart = 0.f;
    float uacc[4] = {};
    const int sh = (t >= 256) ? 4 : 0;     // phase3 slot-half
    const int e  = t & 255;
    const int e4 = e >> 2, eo = e & 3;
    const int ks = t >> 5;                 // phase1 k-slice (= warp id)
    const int pn = t & 31;                 // phase1 n (= lane)

    for (int j = 0; j < NTILE; ++j){
        int buf = j & 1;
        asm volatile("cp.async.wait_group 0;" ::: "memory");
        __syncthreads();                                   // S1: tile ready, prior reads done
        // Safe to issue now: buf^1 was last READ in phase3 of iter j-1,
        // and every thread completed those reads before passing S1.
        if (j + 1 < NTILE) PREFETCH(j + 1, buf ^ 1);
        const float* Xb = Xs + buf*8192;

        // ---- phase 1: logits partials; warp = k-slice (16 k), lane = n ----
        {
            float acc[8] = {};
#pragma unroll
            for (int i = 0; i < 4; ++i){
                int k4 = ks*4 + i;
                float4 x4 = *(const float4*)&Xb[(pn*64 + (k4 ^ (pn & 7)))*4];
                int k = k4*4;
                float xv[4] = {x4.x, x4.y, x4.z, x4.w};
#pragma unroll
                for (int d = 0; d < 4; ++d){
                    float4 qa = *(const float4*)&qT[(k+d)*8];
                    float4 qb = *(const float4*)&qT[(k+d)*8 + 4];
                    acc[0] += xv[d]*qa.x; acc[1] += xv[d]*qa.y;
                    acc[2] += xv[d]*qa.z; acc[3] += xv[d]*qa.w;
                    acc[4] += xv[d]*qb.x; acc[5] += xv[d]*qb.y;
                    acc[6] += xv[d]*qb.z; acc[7] += xv[d]*qb.w;
                }
            }
#pragma unroll
            for (int s = 0; s < 8; ++s) lgp[ks*256 + s*32 + pn] = acc[s];
        }
        __syncthreads();                                   // S2: lgp ready

        // ---- phase 2: online softmax; warp w<8 owns slot w, lane = key ----
        if (w < 8){
            float lg = 0.f;
#pragma unroll
            for (int kq = 0; kq < 16; ++kq) lg += lgp[kq*256 + w*32 + l];
            float mv = warpMax(lg);
            float m_new = fmaxf(m_run, mv);
            float ev = __expf(lg - m_new);
            atT[l*12 + w] = ev;
            float sc = __expf(m_run - m_new);
            lpart = lpart*sc + ev;        // per-lane partial; reduced once at end
            m_run = m_new;
            if (l == 0) scs[w] = sc;
        }
        __syncthreads();                                   // S3: atT/scs ready

        // ---- phase 3: U accumulation; halves own slots sh..sh+3, col e ----
        {
            float4 sv = *(const float4*)&scs[sh];
            uacc[0] *= sv.x; uacc[1] *= sv.y; uacc[2] *= sv.z; uacc[3] *= sv.w;
#pragma unroll 4
            for (int n = 0; n < TN; ++n){
                float x = Xb[(n*64 + (e4 ^ (n & 7)))*4 + eo];
                float4 a = *(const float4*)&atT[n*12 + sh];
                uacc[0] += a.x*x; uacc[1] += a.y*x; uacc[2] += a.z*x; uacc[3] += a.w*x;
            }
        }
    }
#undef PREFETCH

#pragma unroll
    for (int i = 0; i < 4; ++i)
        upart[((size_t)g*ROWS + b*SS + sh + i)*IND + e] = uacc[i];
    if (w < 8){
        float l_run = warpSum(lpart);
        if (l == 0){
            int row = b*SS + w;
            mbuf[(size_t)g*ROWS + row] = m_run;
            lbuf[(size_t)g*ROWS + row] = l_run;
        }
    }
}

// ============ gemmT4: coalesced transposed-weight GEMM, splitK-4, 2 barriers ======
// All 512 threads. WT is [256 k][256 out]. On return, threads with t<128 hold
// combined acc[r][0..1] for output cols c0 = (t&127)*2 (+1).
__device__ __forceinline__ void gemmT4(const float (*sA)[DD], const float* __restrict__ WT,
                                       float* __restrict__ sRed, float acc[4][2], int t)
{
    int cp = t & 127, ks = t >> 7;
    int c0 = cp*2;
    const float2* Wp = reinterpret_cast<const float2*>(WT);
    int kb = ks*64;
    float a00=0,a01=0,a10=0,a11=0,a20=0,a21=0,a30=0,a31=0;
    __syncthreads();    // orders sA (and prior sRed reads) before use
#pragma unroll 4
    for (int k4 = 0; k4 < 16; ++k4){
        int k = kb + k4*4;
        float4 s0 = *(const float4*)&sA[0][k];
        float4 s1 = *(const float4*)&sA[1][k];
        float4 s2 = *(const float4*)&sA[2][k];
        float4 s3 = *(const float4*)&sA[3][k];
        float2 w0 = __ldg(&Wp[(size_t)(k+0)*128 + cp]);
        float2 w1 = __ldg(&Wp[(size_t)(k+1)*128 + cp]);
        float2 w2 = __ldg(&Wp[(size_t)(k+2)*128 + cp]);
        float2 w3 = __ldg(&Wp[(size_t)(k+3)*128 + cp]);
        a00 += s0.x*w0.x + s0.y*w1.x + s0.z*w2.x + s0.w*w3.x;
        a01 += s0.x*w0.y + s0.y*w1.y + s0.z*w2.y + s0.w*w3.y;
        a10 += s1.x*w0.x + s1.y*w1.x + s1.z*w2.x + s1.w*w3.x;
        a11 += s1.x*w0.y + s1.y*w1.y + s1.z*w2.y + s1.w*w3.y;
        a20 += s2.x*w0.x + s2.y*w1.x + s2.z*w2.x + s2.w*w3.x;
        a21 += s2.x*w0.y + s2.y*w1.y + s2.z*w2.y + s2.w*w3.y;
        a30 += s3.x*w0.x + s3.y*w1.x + s3.z*w2.x + s3.w*w3.x;
        a31 += s3.x*w0.y + s3.y*w1.y + s3.z*w2.y + s3.w*w3.y;
    }
    if (ks){
        float* rp = sRed + (size_t)(ks-1)*1024;
        rp[0*256 + c0] = a00; rp[0*256 + c0+1] = a01;
        rp[1*256 + c0] = a10; rp[1*256 + c0+1] = a11;
        rp[2*256 + c0] = a20; rp[2*256 + c0+1] = a21;
        rp[3*256 + c0] = a30; rp[3*256 + c0+1] = a31;
    }
    __syncthreads();
    if (!ks){
        acc[0][0]=a00; acc[0][1]=a01; acc[1][0]=a10; acc[1][1]=a11;
        acc[2][0]=a20; acc[2][1]=a21; acc[3][0]=a30; acc[3][1]=a31;
#pragma unroll
        for (int s = 0; s < 3; ++s){
            const float* rp = sRed + (size_t)s*1024;
#pragma unroll
            for (int r = 0; r < 4; ++r){
                acc[r][0] += rp[r*256 + c0];
                acc[r][1] += rp[r*256 + c0+1];
            }
        }
    }
}

// gemmT_gru: two independent 256-thread GEMMs running concurrently (splitK-2 each).
// Group = t/256; within group: cp=(t&127), ks2=((t>>7)&1). Result (+bias) stored to dstS.
__device__ __forceinline__ void gemmT_gru(const float (*sA)[DD], const float* __restrict__ WT,
                                          float* __restrict__ sRed, float* __restrict__ dstS,
                                          const float* __restrict__ bias, int t)
{
    int tg = t & 255;
    int cp = tg & 127, ks = tg >> 7;
    int c0 = cp*2;
    const float2* Wp = reinterpret_cast<const float2*>(WT);
    int kb = ks*128;
    float a00=0,a01=0,a10=0,a11=0,a20=0,a21=0,a30=0,a31=0;
    __syncthreads();
#pragma unroll 4
    for (int k4 = 0; k4 < 32; ++k4){
        int k = kb + k4*4;
        float4 s0 = *(const float4*)&sA[0][k];
        float4 s1 = *(const float4*)&sA[1][k];
        float4 s2 = *(const float4*)&sA[2][k];
        float4 s3 = *(const float4*)&sA[3][k];
        float2 w0 = __ldg(&Wp[(size_t)(k+0)*128 + cp]);
        float2 w1 = __ldg(&Wp[(size_t)(k+1)*128 + cp]);
        float2 w2 = __ldg(&Wp[(size_t)(k+2)*128 + cp]);
        float2 w3 = __ldg(&Wp[(size_t)(k+3)*128 + cp]);
        a00 += s0.x*w0.x + s0.y*w1.x + s0.z*w2.x + s0.w*w3.x;
        a01 += s0.x*w0.y + s0.y*w1.y + s0.z*w2.y + s0.w*w3.y;
        a10 += s1.x*w0.x + s1.y*w1.x + s1.z*w2.x + s1.w*w3.x;
        a11 += s1.x*w0.y + s1.y*w1.y + s1.z*w2.y + s1.w*w3.y;
        a20 += s2.x*w0.x + s2.y*w1.x + s2.z*w2.x + s2.w*w3.x;
        a21 += s2.x*w0.y + s2.y*w1.y + s2.z*w2.y + s2.w*w3.y;
        a30 += s3.x*w0.x + s3.y*w1.x + s3.z*w2.x + s3.w*w3.x;
        a31 += s3.x*w0.y + s3.y*w1.y + s3.z*w2.y + s3.w*w3.y;
    }
    if (ks){
        sRed[0*256 + c0] = a00; sRed[0*256 + c0+1] = a01;
        sRed[1*256 + c0] = a10; sRed[1*256 + c0+1] = a11;
        sRed[2*256 + c0] = a20; sRed[2*256 + c0+1] = a21;
        sRed[3*256 + c0] = a30; sRed[3*256 + c0+1] = a31;
    }
    __syncthreads();
    if (!ks){
        float b0 = __ldg(&bias[c0]), b1 = __ldg(&bias[c0+1]);
        dstS[0*256 + c0] = a00 + sRed[0*256 + c0] + b0;
        dstS[0*256 + c0+1] = a01 + sRed[0*256 + c0+1] + b1;
        dstS[1*256 + c0] = a10 + sRed[1*256 + c0] + b0;
        dstS[1*256 + c0+1] = a11 + sRed[1*256 + c0+1] + b1;
        dstS[2*256 + c0] = a20 + sRed[2*256 + c0] + b0;
        dstS[2*256 + c0+1] = a21 + sRed[2*256 + c0+1] + b1;
        dstS[3*256 + c0] = a30 + sRed[3*256 + c0] + b0;
        dstS[3*256 + c0+1] = a31 + sRed[3*256 + c0+1] + b1;
    }
}

// ============ POST, 512 threads: transposed-weight GEMMs, minimal barriers ============
__global__ __launch_bounds__(512) void post_kernel(
        const float* __restrict__ upart,
        const float* __restrict__ mbuf, const float* __restrict__ lbuf,
        const float* __restrict__ wT,
        const float* __restrict__ bv,
        const float* __restrict__ b_ih, const float* __restrict__ b_hh,
        const float* __restrict__ lng,  const float* __restrict__ lnb,
        const float* __restrict__ b1,   const float* __restrict__ b2,
        const float* __restrict__ slots_in,
        float* __restrict__ dst)
{
    extern __shared__ float dsm[];
    float (*sBufA)[DD] = (float(*)[DD])(dsm);           // 1024  U / ln
    float (*sprev)[DD] = (float(*)[DD])(dsm + 1024);    // 1024
    float (*sBufB)[DD] = (float(*)[DD])(dsm + 2048);    // 1024  upd / hidden
    float* sGi         = dsm + 3072;                    // 3072
    float* sGh         = dsm + 6144;                    // 3072
    float* sVn         = dsm + 9216;                    // 1024
    float* sRed        = dsm + 10240;                   // 3072

    __shared__ float ssc[4][17];
    __shared__ float sinv[4];

    int r0 = blockIdx.x * 4;
    int t  = threadIdx.x;
    int tc = t & 255, grp = t >> 8;
    int w  = t >> 5, l = t & 31;
    int cp = t & 127, c0 = cp*2;

    // 1. per-row combine scales over NG=16 groups (warps 0-3, lanes 0-15)
    if (w < 4){
        int row = r0 + w;
        float mv = (l < NG) ? __ldg(&mbuf[(size_t)l*ROWS + row]) : -3.4e38f;
        float mm = mv;
        mm = fmaxf(mm, __shfl_xor_sync(0xffffffffu, mm, 1));
        mm = fmaxf(mm, __shfl_xor_sync(0xffffffffu, mm, 2));
        mm = fmaxf(mm, __shfl_xor_sync(0xffffffffu, mm, 4));
        mm = fmaxf(mm, __shfl_xor_sync(0xffffffffu, mm, 8));
        float e  = (l < NG) ? __expf(mv - mm) : 0.f;
        float lv = (l < NG) ? __ldg(&lbuf[(size_t)l*ROWS + row]) * e : 0.f;
        lv += __shfl_xor_sync(0xffffffffu, lv, 1);
        lv += __shfl_xor_sync(0xffffffffu, lv, 2);
        lv += __shfl_xor_sync(0xffffffffu, lv, 4);
        lv += __shfl_xor_sync(0xffffffffu, lv, 8);
        if (l < NG) ssc[w][l] = e;
        if (l == 0) sinv[w] = 1.f / lv;
    }
    __syncthreads();

    // 2. U = (sum_g Ubar_g*sc_g)*inv ; load slots_prev (each thread 2 rows)
#pragma unroll
    for (int rr = 0; rr < 2; ++rr){
        int r = grp*2 + rr, row = r0 + r;
        float a = 0.f;
#pragma unroll
        for (int ch = 0; ch < NG; ++ch)
            a += __ldg(&upart[((size_t)ch*ROWS + row)*IND + tc]) * ssc[r][ch];
        sBufA[r][tc] = a * sinv[r];
        sprev[r][tc] = slots_in[(size_t)row*DD + tc];
    }
    // (leading sync inside gemmT4 orders these writes)

    // 3. upd = U @ Wv^T + bv
    float acc[4][2];
    gemmT4(sBufA, wT + 0*DD*DD, sRed, acc, t);
    if (t < 128){
        float b0 = __ldg(&bv[c0]), bb1 = __ldg(&bv[c0+1]);
#pragma unroll
        for (int r = 0; r < 4; ++r){
            sBufB[r][c0]   = acc[r][0] + b0;
            sBufB[r][c0+1] = acc[r][1] + bb1;
        }
    }

    // 4. GRU gates: grp0 -> gi (W_ih on upd), grp1 -> gh (W_hh on prev), concurrent
#pragma unroll
    for (int j = 0; j < 3; ++j){
        const float (*Ag)[DD] = (grp == 0) ? sBufB : sprev;
        const float* Wg = (grp == 0) ? (wT + (size_t)(1+j)*DD*DD) : (wT + (size_t)(4+j)*DD*DD);
        float* dS = (grp == 0) ? (sGi + j*1024) : (sGh + j*1024);
        const float* bb = (grp == 0) ? (b_ih + j*256) : (b_hh + j*256);
        float* rS = (grp == 0) ? sRed : (sRed + 1024);
        gemmT_gru(Ag, Wg, rS, dS, bb, t);
    }
    __syncthreads();   // gate stores (after last internal barrier) -> visible

    // 5. GRU cell + residual (threads t<256, col tc=t)
    float vnew[4] = {0.f, 0.f, 0.f, 0.f};
    if (grp == 0){
#pragma unroll
        for (int r = 0; r < 4; ++r){
            float ir = sGi[0*1024 + r*256 + tc];
            float iz = sGi[1*1024 + r*256 + tc];
            float in_= sGi[2*1024 + r*256 + tc];
            float hr = sGh[0*1024 + r*256 + tc];
            float hz = sGh[1*1024 + r*256 + tc];
            float hn = sGh[2*1024 + r*256 + tc];
            float rr = 1.f / (1.f + expf(-(ir + hr)));
            float zz = 1.f / (1.f + expf(-(iz + hz)));
            float nn = tanhf(in_ + rr*hn);
            float h  = sprev[r][tc];
            vnew[r]  = h + (1.f - zz)*nn + zz*h;
        }
    }

    // 6. LN(vnew) -> sBufA ; stash vnew -> sVn
    float lnv[4];
    block_ln4(vnew, lnv, lng, lnb, t);
    if (grp == 0){
#pragma unroll
        for (int r = 0; r < 4; ++r){
            sBufA[r][tc] = lnv[r];
            sVn[r*256 + tc] = vnew[r];
        }
    }

    // 7. hidden = relu(sln @ W1^T + b1)
    gemmT4(sBufA, wT + (size_t)7*DD*DD, sRed, acc, t);
    if (t < 128){
        float b0 = __ldg(&b1[c0]), bb1 = __ldg(&b1[c0+1]);
#pragma unroll
        for (int r = 0; r < 4; ++r){
            sBufB[r][c0]   = fmaxf(acc[r][0] + b0, 0.f);
            sBufB[r][c0+1] = fmaxf(acc[r][1] + bb1, 0.f);
        }
    }

    // 8. out = vnew + hidden @ W2^T + b2
    gemmT4(sBufB, wT + (size_t)8*DD*DD, sRed, acc, t);
    if (t < 128){
        float b0 = __ldg(&b2[c0]), bb1 = __ldg(&b2[c0+1]);
#pragma unroll
        for (int r = 0; r < 4; ++r){
            dst[(size_t)(r0+r)*DD + c0]   = sVn[r*256 + c0]   + acc[r][0] + b0;
            dst[(size_t)(r0+r)*DD + c0+1] = sVn[r*256 + c0+1] + acc[r][1] + bb1;
        }
    }
}

// ------------------------- host launcher -------------------------
extern "C" void kernel_launch(void* const* d_in, const int* in_sizes, int n_in,
                              void* d_out, int out_size)
{
    const float* inputs = (const float*)d_in[0];
    const float* noise  = (const float*)d_in[1];
    const float* s_mu   = (const float*)d_in[2];
    const float* s_sig  = (const float*)d_in[3];
    const float* Wq = (const float*)d_in[4];  const float* bq = (const float*)d_in[5];
    const float* Wk = (const float*)d_in[6];  /* bk = d_in[7] : dead (softmax shift-invariance) */
    const float* Wv = (const float*)d_in[8];  const float* bv = (const float*)d_in[9];
    const float* W_ih = (const float*)d_in[10]; const float* b_ih = (const float*)d_in[11];
    const float* W_hh = (const float*)d_in[12]; const float* b_hh = (const float*)d_in[13];
    const float* W1 = (const float*)d_in[14]; const float* b1 = (const float*)d_in[15];
    const float* W2 = (const float*)d_in[16]; const float* b2 = (const float*)d_in[17];
    const float* lnsg = (const float*)d_in[18]; const float* lnsb = (const float*)d_in[19];
    const float* lnmg = (const float*)d_in[20]; const float* lnmb = (const float*)d_in[21];
    float* out = (float*)d_out;
    (void)in_sizes; (void)n_in; (void)out_size;

    float *slots, *qW, *upart, *mbuf, *lbuf, *wT;
    cudaGetSymbolAddress((void**)&slots, g_slots);
    cudaGetSymbolAddress((void**)&qW,    g_qW);
    cudaGetSymbolAddress((void**)&upart, g_upart);
    cudaGetSymbolAddress((void**)&mbuf,  g_m);
    cudaGetSymbolAddress((void**)&lbuf,  g_l);
    cudaGetSymbolAddress((void**)&wT,    g_wT);

    const int ATTN_SMEM = (16384 + 2048 + 4096 + 384 + 8) * 4;   // 91,680 B -> 2 blocks/SM
    const int POST_SMEM = 13312 * 4;                             // 53,248 B
    static int s_init = 0;
    if (!s_init){
        cudaFuncSetAttribute(attn_kernel, cudaFuncAttributeMaxDynamicSharedMemorySize, ATTN_SMEM);
        cudaFuncSetAttribute(post_kernel, cudaFuncAttributeMaxDynamicSharedMemorySize, POST_SMEM);
        s_init = 1;
    }

    dim3 gBN(BB, NG);

    init_slots_kernel<<<ROWS, 256>>>(noise, s_mu, s_sig, slots);
    transpose_kernel<<<9*64, 256>>>(Wv, W_ih, W_hh, W1, W2, wT);

    for (int it = 0; it < 3; ++it){
        pre_kernel<<<ROWS/4, 256>>>(slots, lnsg, lnsb, Wq, bq, Wk, qW);
        attn_kernel<<<gBN, 512, ATTN_SMEM>>>(qW, inputs, upart, mbuf, lbuf);
        float* dst = (it == 2) ? out : slots;
        post_kernel<<<ROWS/4, 512, POST_SMEM>>>(upart, mbuf, lbuf, wT, bv, b_ih, b_hh,
                                                lnmg, lnmb, b1, b2, slots, dst);
    }
}

// round 11
// speedup vs baseline: 1.1021x; 1.1021x over previous
#include <cuda_runtime.h>
#include <math.h>
#include <stdint.h>

// Problem constants
#define BB   64
#define NN   4096
#define IND  256
#define SS   8
#define DD   256
#define ROWS (BB*SS)        // 512
#define NG   16             // attention groups (blocks.y)
#define TN   32             // n's per tile
#define NTILE 8             // tiles per block (NG*NTILE*TN = 4096)

// -------- scratch (device globals; no allocation allowed) --------
__device__ float g_slots [ROWS*DD];
__device__ float g_qW    [ROWS*IND];
__device__ float g_upart [NG*ROWS*IND];   // unnormalized U partials (8 MB)
__device__ float g_m     [NG*ROWS];
__device__ float g_l     [NG*ROWS];

// -------- reductions --------
__device__ __forceinline__ float warpSum(float v){
#pragma unroll
    for (int o = 16; o > 0; o >>= 1) v += __shfl_xor_sync(0xffffffffu, v, o);
    return v;
}
__device__ __forceinline__ float warpMax(float v){
#pragma unroll
    for (int o = 16; o > 0; o >>= 1) v = fmaxf(v, __shfl_xor_sync(0xffffffffu, v, o));
    return v;
}

// -------- slots = mu + sigma * noise --------
__global__ void init_slots_kernel(const float* __restrict__ noise,
                                  const float* __restrict__ mu,
                                  const float* __restrict__ sigma,
                                  float* __restrict__ slots){
    int i  = blockIdx.x * 256 + threadIdx.x;
    int sd = i & (SS*DD - 1);
    slots[i] = mu[sd] + sigma[sd] * noise[i];
}

// Block LayerNorm (256-thread data path; callable from 256 OR 512 threads).
__device__ __forceinline__ void block_ln4(const float v[4], float o[4],
                                          const float* __restrict__ g,
                                          const float* __restrict__ b, int t)
{
    __shared__ float part[8][4];
    __shared__ float stat[4];
    int w = t >> 5, l = t & 31;
#pragma unroll
    for (int r = 0; r < 4; ++r){
        float p = warpSum(v[r]);
        if (l == 0 && w < 8) part[w][r] = p;
    }
    __syncthreads();
    if (t < 32){
        int rr = l >> 3, ww = l & 7;
        float x = part[ww][rr];
        x += __shfl_xor_sync(0xffffffffu, x, 1);
        x += __shfl_xor_sync(0xffffffffu, x, 2);
        x += __shfl_xor_sync(0xffffffffu, x, 4);
        if (ww == 0) stat[rr] = x * (1.f/256.f);
    }
    __syncthreads();
    float d[4];
#pragma unroll
    for (int r = 0; r < 4; ++r) d[r] = v[r] - stat[r];
    __syncthreads();
#pragma unroll
    for (int r = 0; r < 4; ++r){
        float p = warpSum(d[r]*d[r]);
        if (l == 0 && w < 8) part[w][r] = p;
    }
    __syncthreads();
    if (t < 32){
        int rr = l >> 3, ww = l & 7;
        float x = part[ww][rr];
        x += __shfl_xor_sync(0xffffffffu, x, 1);
        x += __shfl_xor_sync(0xffffffffu, x, 2);
        x += __shfl_xor_sync(0xffffffffu, x, 4);
        if (ww == 0) stat[rr] = rsqrtf(x * (1.f/256.f) + 1e-5f);
    }
    __syncthreads();
    int tc = t & 255;
    float gg = g[tc], bb = b[tc];
#pragma unroll
    for (int r = 0; r < 4; ++r) o[r] = d[r] * stat[r] * gg + bb;
}

// ============ PRE: LN(slots) -> q=ln@Wq^T+bq -> qW=(q@Wk)*inv_sqrt_d ============
__global__ __launch_bounds__(256) void pre_kernel(
        const float* __restrict__ slots,
        const float* __restrict__ lng, const float* __restrict__ lnb,
        const float* __restrict__ Wq,  const float* __restrict__ bq,
        const float* __restrict__ Wk,
        float* __restrict__ qW)
{
    int r0 = blockIdx.x * 4;
    int t  = threadIdx.x;
    __shared__ float s_ln[4][DD];
    __shared__ float s_q [4][DD];

    float v[4];
#pragma unroll
    for (int r = 0; r < 4; ++r) v[r] = slots[(size_t)(r0+r)*DD + t];
    float o[4];
    block_ln4(v, o, lng, lnb, t);
#pragma unroll
    for (int r = 0; r < 4; ++r) s_ln[r][t] = o[r];
    __syncthreads();

    {   // q[r, n=t] = s_ln[r] . Wq[t,:] + bq[t]
        const float4* wrow = reinterpret_cast<const float4*>(Wq + (size_t)t*DD);
        float a0=0.f, a1=0.f, a2=0.f, a3=0.f;
#pragma unroll 8
        for (int k4 = 0; k4 < 64; ++k4){
            float4 wv = __ldg(&wrow[k4]);
            int k = k4*4;
            a0 += s_ln[0][k]*wv.x + s_ln[0][k+1]*wv.y + s_ln[0][k+2]*wv.z + s_ln[0][k+3]*wv.w;
            a1 += s_ln[1][k]*wv.x + s_ln[1][k+1]*wv.y + s_ln[1][k+2]*wv.z + s_ln[1][k+3]*wv.w;
            a2 += s_ln[2][k]*wv.x + s_ln[2][k+1]*wv.y + s_ln[2][k+2]*wv.z + s_ln[2][k+3]*wv.w;
            a3 += s_ln[3][k]*wv.x + s_ln[3][k+1]*wv.y + s_ln[3][k+2]*wv.z + s_ln[3][k+3]*wv.w;
        }
        float bv = __ldg(&bq[t]);
        s_q[0][t] = a0 + bv; s_q[1][t] = a1 + bv;
        s_q[2][t] = a2 + bv; s_q[3][t] = a3 + bv;
    }
    __syncthreads();

    {   // qW[r, e=t] = (s_q[r] @ Wk[:,t]) / 16
        float c0=0.f, c1=0.f, c2=0.f, c3=0.f;
#pragma unroll 8
        for (int d = 0; d < DD; ++d){
            float wv = __ldg(&Wk[(size_t)d*IND + t]);
            c0 += s_q[0][d]*wv; c1 += s_q[1][d]*wv;
            c2 += s_q[2][d]*wv; c3 += s_q[3][d]*wv;
        }
        qW[(size_t)(r0+0)*IND + t] = c0 * 0.0625f;
        qW[(size_t)(r0+1)*IND + t] = c1 * 0.0625f;
        qW[(size_t)(r0+2)*IND + t] = c2 * 0.0625f;
        qW[(size_t)(r0+3)*IND + t] = c3 * 0.0625f;
    }
}

// ============ FLASH attention, TN=32 tiles, 2 blocks/SM, hoisted swizzle math ========
__global__ __launch_bounds__(512, 2) void attn_kernel(
        const float* __restrict__ qW,
        const float* __restrict__ inputs,
        float* __restrict__ upart,
        float* __restrict__ mbuf,
        float* __restrict__ lbuf)
{
    extern __shared__ float dsm[];
    float* Xs  = dsm;                  // 2 * 8192 floats (64 KB)
    float* qT  = dsm + 16384;          // [k][s] 2048
    float* lgp = qT  + 2048;           // [ks][s][n] 16*8*32 = 4096
    float* atT = lgp + 4096;           // [n][12] 384
    float* scs = atT + 384;            // 8

    int b = blockIdx.x, g = blockIdx.y;
    int t = threadIdx.x, w = t >> 5, l = t & 31;

    // stage qT
#pragma unroll
    for (int p = 0; p < 4; ++p){
        int idx = t + p*512;
        qT[(idx & 255)*8 + (idx >> 8)] = qW[(size_t)b*2048 + idx];
    }

    const float* src0 = inputs + ((size_t)b*NN + g*(NTILE*TN))*IND;
#define PREFETCH(j, buf) do {                                                   \
        const float* _s = src0 + (size_t)(j)*TN*IND;                            \
        float* _d = Xs + (buf)*8192;                                            \
        _Pragma("unroll")                                                       \
        for (int p = 0; p < 4; ++p){                                            \
            int idx = t + p*512;                                                \
            int n = idx >> 6, k4 = idx & 63;                                    \
            uint32_t sa = (uint32_t)__cvta_generic_to_shared(                   \
                              &_d[(n*64 + (k4 ^ (n & 7)))*4]);                  \
            asm volatile("cp.async.cg.shared.global [%0], [%1], 16;"            \
                         :: "r"(sa), "l"(_s + (size_t)n*IND + k4*4) : "memory");\
        }                                                                       \
        asm volatile("cp.async.commit_group;" ::: "memory");                    \
    } while(0)

    PREFETCH(0, 0);

    float m_run = -3.4e38f, lpart = 0.f;
    float uacc[4] = {};
    const int sh = (t >= 256) ? 4 : 0;     // phase3 slot-half
    const int e  = t & 255;
    const int e4 = e >> 2, eo = e & 3;
    const int ks = t >> 5;                 // phase1 k-slice (= warp id)
    const int pn = t & 31;                 // phase1 n (= lane)

    // ---- hoisted swizzle address math ----
    // phase1: float index of (n=pn, k4=ks*4+i) = pn*256 + (((ks*4)^(c&4)) + (i^(c&3)))*4
    const int c  = pn & 7;
    const int p1base = pn*256 + ((ks*4) ^ (c & 4))*4;
    int a1[4];
#pragma unroll
    for (int i = 0; i < 4; ++i) a1[i] = p1base + (i ^ (c & 3))*4;
    // phase3: float index of (n, e) = n*256 + off3[n&7]
    int off3[8];
#pragma unroll
    for (int cc = 0; cc < 8; ++cc) off3[cc] = (e4 ^ cc)*4 + eo;

    for (int j = 0; j < NTILE; ++j){
        int buf = j & 1;
        asm volatile("cp.async.wait_group 0;" ::: "memory");
        __syncthreads();                                   // S1: tile ready, prior reads done
        if (j + 1 < NTILE) PREFETCH(j + 1, buf ^ 1);
        const float* Xb = Xs + buf*8192;

        // ---- phase 1: logits partials; warp = k-slice (16 k), lane = n ----
        {
            float acc[8] = {};
#pragma unroll
            for (int i = 0; i < 4; ++i){
                float4 x4 = *(const float4*)&Xb[a1[i]];
                int k = (ks*4 + i)*4;
                float xv[4] = {x4.x, x4.y, x4.z, x4.w};
#pragma unroll
                for (int d = 0; d < 4; ++d){
                    float4 qa = *(const float4*)&qT[(k+d)*8];
                    float4 qb = *(const float4*)&qT[(k+d)*8 + 4];
                    acc[0] += xv[d]*qa.x; acc[1] += xv[d]*qa.y;
                    acc[2] += xv[d]*qa.z; acc[3] += xv[d]*qa.w;
                    acc[4] += xv[d]*qb.x; acc[5] += xv[d]*qb.y;
                    acc[6] += xv[d]*qb.z; acc[7] += xv[d]*qb.w;
                }
            }
#pragma unroll
            for (int s = 0; s < 8; ++s) lgp[ks*256 + s*32 + pn] = acc[s];
        }
        __syncthreads();                                   // S2: lgp ready

        // ---- phase 2: online softmax; warp w<8 owns slot w, lane = key ----
        if (w < 8){
            float lg = 0.f;
#pragma unroll
            for (int kq = 0; kq < 16; ++kq) lg += lgp[kq*256 + w*32 + l];
            float mv = warpMax(lg);
            float m_new = fmaxf(m_run, mv);
            float ev = __expf(lg - m_new);
            atT[l*12 + w] = ev;
            float sc = __expf(m_run - m_new);
            lpart = lpart*sc + ev;        // per-lane partial; reduced once at end
            m_run = m_new;
            if (l == 0) scs[w] = sc;
        }
        __syncthreads();                                   // S3: atT/scs ready

        // ---- phase 3: U accumulation; halves own slots sh..sh+3, col e ----
        {
            float4 sv = *(const float4*)&scs[sh];
            uacc[0] *= sv.x; uacc[1] *= sv.y; uacc[2] *= sv.z; uacc[3] *= sv.w;
            for (int n8 = 0; n8 < TN; n8 += 8){
#pragma unroll
                for (int cc = 0; cc < 8; ++cc){
                    int n = n8 + cc;
                    float x = Xb[n*256 + off3[cc]];
                    float4 a = *(const float4*)&atT[n*12 + sh];
                    uacc[0] += a.x*x; uacc[1] += a.y*x;
                    uacc[2] += a.z*x; uacc[3] += a.w*x;
                }
            }
        }
    }
#undef PREFETCH

#pragma unroll
    for (int i = 0; i < 4; ++i)
        upart[((size_t)g*ROWS + b*SS + sh + i)*IND + e] = uacc[i];
    if (w < 8){
        float l_run = warpSum(lpart);
        if (l == 0){
            int row = b*SS + w;
            mbuf[(size_t)g*ROWS + row] = m_run;
            lbuf[(size_t)g*ROWS + row] = l_run;
        }
    }
}

// ============ gemm_tiles: register-double-buffered, group-local staging (R8 best) ====
__device__ __forceinline__ void gemm_tiles(
        const float (*sA)[DD],
        const float* __restrict__ W,
        float* __restrict__ sWt,     // this group's staging [32][257]
        float acc[4], int tc, int ktStart, int ktCount)
{
    const float4* Wp = reinterpret_cast<const float4*>(W);
    float4 r[8];
#pragma unroll
    for (int p = 0; p < 8; ++p){
        int idx = tc + p*256;
        r[p] = __ldg(&Wp[(size_t)(idx >> 3)*64 + ktStart*8 + (idx & 7)]);
    }
    acc[0] = acc[1] = acc[2] = acc[3] = 0.f;

    for (int kt = 0; kt < ktCount; ++kt){
        __syncthreads();
#pragma unroll
        for (int p = 0; p < 8; ++p){
            int idx  = tc + p*256;
            int orow = idx >> 3, k4 = idx & 7;
            sWt[(k4*4+0)*257 + orow] = r[p].x;
            sWt[(k4*4+1)*257 + orow] = r[p].y;
            sWt[(k4*4+2)*257 + orow] = r[p].z;
            sWt[(k4*4+3)*257 + orow] = r[p].w;
        }
        __syncthreads();
        if (kt + 1 < ktCount){
#pragma unroll
            for (int p = 0; p < 8; ++p){
                int idx = tc + p*256;
                r[p] = __ldg(&Wp[(size_t)(idx >> 3)*64 + (ktStart+kt+1)*8 + (idx & 7)]);
            }
        }
        int kb = (ktStart + kt)*32;
#pragma unroll
        for (int kk = 0; kk < 8; ++kk){
            float4 a0 = *(const float4*)&sA[0][kb + kk*4];
            float4 a1 = *(const float4*)&sA[1][kb + kk*4];
            float4 a2 = *(const float4*)&sA[2][kb + kk*4];
            float4 a3 = *(const float4*)&sA[3][kb + kk*4];
            float x0 = sWt[(kk*4+0)*257 + tc];
            float x1 = sWt[(kk*4+1)*257 + tc];
            float x2 = sWt[(kk*4+2)*257 + tc];
            float x3 = sWt[(kk*4+3)*257 + tc];
            acc[0] += a0.x*x0 + a0.y*x1 + a0.z*x2 + a0.w*x3;
            acc[1] += a1.x*x0 + a1.y*x1 + a1.z*x2 + a1.w*x3;
            acc[2] += a2.x*x0 + a2.y*x1 + a2.z*x2 + a2.w*x3;
            acc[3] += a3.x*x0 + a3.y*x1 + a3.z*x2 + a3.w*x3;
        }
    }
}

// ============ POST, 512 threads: split-K GEMMs + concurrent GRU gates (R8 best) ======
__global__ __launch_bounds__(512) void post_kernel(
        const float* __restrict__ upart,
        const float* __restrict__ mbuf, const float* __restrict__ lbuf,
        const float* __restrict__ Wv,   const float* __restrict__ bv,
        const float* __restrict__ W_ih, const float* __restrict__ b_ih,
        const float* __restrict__ W_hh, const float* __restrict__ b_hh,
        const float* __restrict__ lng,  const float* __restrict__ lnb,
        const float* __restrict__ W1,   const float* __restrict__ b1,
        const float* __restrict__ W2,   const float* __restrict__ b2,
        const float* __restrict__ slots_in,
        float* __restrict__ dst)
{
    extern __shared__ float dsm[];
    float (*sBufA)[DD] = (float(*)[DD])(dsm);           // 1024  U / sln
    float (*sprev)[DD] = (float(*)[DD])(dsm + 1024);    // 1024
    float (*sBufB)[DD] = (float(*)[DD])(dsm + 2048);    // 1024  upd / hid
    float* sGh         = dsm + 3072;                    // 3072  gh[3][4][256]
    float (*sPar)[DD]  = (float(*)[DD])(dsm + 6144);    // 1024  split-k partials
    float* sWtA        = dsm + 7168;                    // 8224
    float* sWtB        = dsm + 15392;                   // 8224

    __shared__ float ssc[4][17];
    __shared__ float sinv[4];

    int r0 = blockIdx.x * 4;
    int t  = threadIdx.x;
    int tc = t & 255, grp = t >> 8;
    int w  = t >> 5, l = t & 31;
    float* myWt = grp ? sWtB : sWtA;

    // 1. per-row combine scales over NG=16 groups (warps 0-3, lanes 0-15)
    if (w < 4){
        int row = r0 + w;
        float mv = (l < NG) ? __ldg(&mbuf[(size_t)l*ROWS + row]) : -3.4e38f;
        float mm = mv;
        mm = fmaxf(mm, __shfl_xor_sync(0xffffffffu, mm, 1));
        mm = fmaxf(mm, __shfl_xor_sync(0xffffffffu, mm, 2));
        mm = fmaxf(mm, __shfl_xor_sync(0xffffffffu, mm, 4));
        mm = fmaxf(mm, __shfl_xor_sync(0xffffffffu, mm, 8));
        float e  = (l < NG) ? __expf(mv - mm) : 0.f;
        float lv = (l < NG) ? __ldg(&lbuf[(size_t)l*ROWS + row]) * e : 0.f;
        lv += __shfl_xor_sync(0xffffffffu, lv, 1);
        lv += __shfl_xor_sync(0xffffffffu, lv, 2);
        lv += __shfl_xor_sync(0xffffffffu, lv, 4);
        lv += __shfl_xor_sync(0xffffffffu, lv, 8);
        if (l < NG) ssc[w][l] = e;
        if (l == 0) sinv[w] = 1.f / lv;
    }
    __syncthreads();

    // 2. U = (sum_g Ubar_g*sc_g)*inv ; load slots_prev (each thread 2 rows)
#pragma unroll
    for (int rr = 0; rr < 2; ++rr){
        int r = grp*2 + rr, row = r0 + r;
        float a = 0.f;
#pragma unroll
        for (int ch = 0; ch < NG; ++ch)
            a += __ldg(&upart[((size_t)ch*ROWS + row)*IND + tc]) * ssc[r][ch];
        sBufA[r][tc] = a * sinv[r];
        sprev[r][tc] = slots_in[(size_t)row*DD + tc];
    }
    // (first barrier inside gemm_tiles orders these writes)

    // 3. upd = U @ Wv^T + bv  (split-K)
    float acc[4];
    gemm_tiles(sBufA, Wv, myWt, acc, tc, grp*4, 4);
    if (grp == 1){
#pragma unroll
        for (int r = 0; r < 4; ++r) sPar[r][tc] = acc[r];
    }
    __syncthreads();
    if (grp == 0){
        float bb = __ldg(&bv[tc]);
#pragma unroll
        for (int r = 0; r < 4; ++r) sBufB[r][tc] = acc[r] + sPar[r][tc] + bb;
    }

    // 4. GRU gates concurrently: grp0 -> gi (W_ih on upd), grp1 -> gh (W_hh on prev)
    float gi[3][4];
#pragma unroll
    for (int j = 0; j < 3; ++j){
        const float* Wg = grp ? (W_hh + (size_t)j*DD*DD) : (W_ih + (size_t)j*DD*DD);
        const float (*Ag)[DD] = grp ? sprev : sBufB;
        gemm_tiles(Ag, Wg, myWt, acc, tc, 0, 8);
        if (grp == 0){
            float bb = __ldg(&b_ih[tc + j*256]);
#pragma unroll
            for (int r = 0; r < 4; ++r) gi[j][r] = acc[r] + bb;
        } else {
            float bb = __ldg(&b_hh[tc + j*256]);
#pragma unroll
            for (int r = 0; r < 4; ++r) sGh[(j*4 + r)*256 + tc] = acc[r] + bb;
        }
    }
    __syncthreads();

    // 5. GRU cell + residual (grp0)
    float vnew[4] = {0.f, 0.f, 0.f, 0.f};
    if (grp == 0){
#pragma unroll
        for (int r = 0; r < 4; ++r){
            float hr = sGh[(0*4 + r)*256 + tc];
            float hz = sGh[(1*4 + r)*256 + tc];
            float hn = sGh[(2*4 + r)*256 + tc];
            float rr = 1.f / (1.f + expf(-(gi[0][r] + hr)));
            float zz = 1.f / (1.f + expf(-(gi[1][r] + hz)));
            float nn = tanhf(gi[2][r] + rr*hn);
            float h  = sprev[r][tc];
            vnew[r]  = h + (1.f - zz)*nn + zz*h;
        }
    }

    // 6. LN(vnew) -> sBufA (grp0 data; all threads pass barriers)
    float lnv[4];
    block_ln4(vnew, lnv, lng, lnb, t);
    if (grp == 0){
#pragma unroll
        for (int r = 0; r < 4; ++r) sBufA[r][tc] = lnv[r];
    }

    // 7. hidden = relu(sln @ W1^T + b1) -> sBufB (split-K)
    gemm_tiles(sBufA, W1, myWt, acc, tc, grp*4, 4);
    if (grp == 1){
#pragma unroll
        for (int r = 0; r < 4; ++r) sPar[r][tc] = acc[r];
    }
    __syncthreads();
    if (grp == 0){
        float bb = __ldg(&b1[tc]);
#pragma unroll
        for (int r = 0; r < 4; ++r) sBufB[r][tc] = fmaxf(acc[r] + sPar[r][tc] + bb, 0.f);
    }

    // 8. out = vnew + hid @ W2^T + b2 (split-K)
    gemm_tiles(sBufB, W2, myWt, acc, tc, grp*4, 4);
    if (grp == 1){
#pragma unroll
        for (int r = 0; r < 4; ++r) sPar[r][tc] = acc[r];
    }
    __syncthreads();
    if (grp == 0){
        float bb = __ldg(&b2[tc]);
#pragma unroll
        for (int r = 0; r < 4; ++r)
            dst[(size_t)(r0+r)*DD + tc] = vnew[r] + acc[r] + sPar[r][tc] + bb;
    }
}

// ------------------------- host launcher -------------------------
extern "C" void kernel_launch(void* const* d_in, const int* in_sizes, int n_in,
                              void* d_out, int out_size)
{
    const float* inputs = (const float*)d_in[0];
    const float* noise  = (const float*)d_in[1];
    const float* s_mu   = (const float*)d_in[2];
    const float* s_sig  = (const float*)d_in[3];
    const float* Wq = (const float*)d_in[4];  const float* bq = (const float*)d_in[5];
    const float* Wk = (const float*)d_in[6];  /* bk = d_in[7] : dead (softmax shift-invariance) */
    const float* Wv = (const float*)d_in[8];  const float* bv = (const float*)d_in[9];
    const float* W_ih = (const float*)d_in[10]; const float* b_ih = (const float*)d_in[11];
    const float* W_hh = (const float*)d_in[12]; const float* b_hh = (const float*)d_in[13];
    const float* W1 = (const float*)d_in[14]; const float* b1 = (const float*)d_in[15];
    const float* W2 = (const float*)d_in[16]; const float* b2 = (const float*)d_in[17];
    const float* lnsg = (const float*)d_in[18]; const float* lnsb = (const float*)d_in[19];
    const float* lnmg = (const float*)d_in[20]; const float* lnmb = (const float*)d_in[21];
    float* out = (float*)d_out;
    (void)in_sizes; (void)n_in; (void)out_size;

    float *slots, *qW, *upart, *mbuf, *lbuf;
    cudaGetSymbolAddress((void**)&slots, g_slots);
    cudaGetSymbolAddress((void**)&qW,    g_qW);
    cudaGetSymbolAddress((void**)&upart, g_upart);
    cudaGetSymbolAddress((void**)&mbuf,  g_m);
    cudaGetSymbolAddress((void**)&lbuf,  g_l);

    const int ATTN_SMEM = (16384 + 2048 + 4096 + 384 + 8) * 4;   // 91,680 B -> 2 blocks/SM
    const int POST_SMEM = (1024*3 + 3072 + 1024 + 8224*2) * 4;   // 94,464 B
    static int s_init = 0;
    if (!s_init){
        cudaFuncSetAttribute(attn_kernel, cudaFuncAttributeMaxDynamicSharedMemorySize, ATTN_SMEM);
        cudaFuncSetAttribute(post_kernel, cudaFuncAttributeMaxDynamicSharedMemorySize, POST_SMEM);
        s_init = 1;
    }

    dim3 gBN(BB, NG);

    init_slots_kernel<<<ROWS, 256>>>(noise, s_mu, s_sig, slots);

    for (int it = 0; it < 3; ++it){
        pre_kernel<<<ROWS/4, 256>>>(slots, lnsg, lnsb, Wq, bq, Wk, qW);
        attn_kernel<<<gBN, 512, ATTN_SMEM>>>(qW, inputs, upart, mbuf, lbuf);
        float* dst = (it == 2) ? out : slots;
        post_kernel<<<ROWS/4, 512, POST_SMEM>>>(upart, mbuf, lbuf, Wv, bv, W_ih, b_ih, W_hh, b_hh,
                                                lnmg, lnmb, W1, b1, W2, b2, slots, dst);
    }
}

// round 12
// speedup vs baseline: 1.2786x; 1.1601x over previous
#include <cuda_runtime.h>
#include <math.h>
#include <stdint.h>

// Problem constants
#define BB   64
#define NN   4096
#define IND  256
#define SS   8
#define DD   256
#define ROWS (BB*SS)        // 512
#define NG   16             // attention groups (blocks.y)
#define TN   32             // n's per tile
#define NTILE 8             // tiles per block (NG*NTILE*TN = 4096)

// -------- scratch (device globals; no allocation allowed) --------
__device__ float g_slots [ROWS*DD];
__device__ float g_qW    [ROWS*IND];
__device__ float g_upart [NG*ROWS*IND];   // unnormalized U partials (8 MB)
__device__ float g_m     [NG*ROWS];
__device__ float g_l     [NG*ROWS];

// -------- reductions --------
__device__ __forceinline__ float warpSum(float v){
#pragma unroll
    for (int o = 16; o > 0; o >>= 1) v += __shfl_xor_sync(0xffffffffu, v, o);
    return v;
}
__device__ __forceinline__ float warpMax(float v){
#pragma unroll
    for (int o = 16; o > 0; o >>= 1) v = fmaxf(v, __shfl_xor_sync(0xffffffffu, v, o));
    return v;
}

// -------- slots = mu + sigma * noise --------
__global__ void init_slots_kernel(const float* __restrict__ noise,
                                  const float* __restrict__ mu,
                                  const float* __restrict__ sigma,
                                  float* __restrict__ slots){
    int i  = blockIdx.x * 256 + threadIdx.x;
    int sd = i & (SS*DD - 1);
    slots[i] = mu[sd] + sigma[sd] * noise[i];
}

// Block LayerNorm (256-thread data path; callable from 256 OR 512 threads).
__device__ __forceinline__ void block_ln4(const float v[4], float o[4],
                                          const float* __restrict__ g,
                                          const float* __restrict__ b, int t)
{
    __shared__ float part[8][4];
    __shared__ float stat[4];
    int w = t >> 5, l = t & 31;
#pragma unroll
    for (int r = 0; r < 4; ++r){
        float p = warpSum(v[r]);
        if (l == 0 && w < 8) part[w][r] = p;
    }
    __syncthreads();
    if (t < 32){
        int rr = l >> 3, ww = l & 7;
        float x = part[ww][rr];
        x += __shfl_xor_sync(0xffffffffu, x, 1);
        x += __shfl_xor_sync(0xffffffffu, x, 2);
        x += __shfl_xor_sync(0xffffffffu, x, 4);
        if (ww == 0) stat[rr] = x * (1.f/256.f);
    }
    __syncthreads();
    float d[4];
#pragma unroll
    for (int r = 0; r < 4; ++r) d[r] = v[r] - stat[r];
    __syncthreads();
#pragma unroll
    for (int r = 0; r < 4; ++r){
        float p = warpSum(d[r]*d[r]);
        if (l == 0 && w < 8) part[w][r] = p;
    }
    __syncthreads();
    if (t < 32){
        int rr = l >> 3, ww = l & 7;
        float x = part[ww][rr];
        x += __shfl_xor_sync(0xffffffffu, x, 1);
        x += __shfl_xor_sync(0xffffffffu, x, 2);
        x += __shfl_xor_sync(0xffffffffu, x, 4);
        if (ww == 0) stat[rr] = rsqrtf(x * (1.f/256.f) + 1e-5f);
    }
    __syncthreads();
    int tc = t & 255;
    float gg = g[tc], bb = b[tc];
#pragma unroll
    for (int r = 0; r < 4; ++r) o[r] = d[r] * stat[r] * gg + bb;
}

// ============ gemm_tiles v2: row-major staging (STS.128 in, LDS.128 out) ============
// acc[r] = sum over k-tiles [ktStart, ktStart+ktCount) of sA[r][k]*W[tc][k].
// sWt layout: [256 orow][36 floats] (32 k + 4 pad; 36*4B row stride -> 16B aligned,
// and bank(36*l) = 4*l so every 8-lane phase covers all 32 banks).
// MUST be called by all 512 threads with identical ktCount (barriers inside).
__device__ __forceinline__ void gemm_tiles(
        const float (*sA)[DD],
        const float* __restrict__ W,
        float* __restrict__ sWt,     // this group's staging [256][36]
        float acc[4], int tc, int ktStart, int ktCount)
{
    const float4* Wp = reinterpret_cast<const float4*>(W);
    float4 r[8];
#pragma unroll
    for (int p = 0; p < 8; ++p){
        int idx = tc + p*256;
        r[p] = __ldg(&Wp[(size_t)(idx >> 3)*64 + ktStart*8 + (idx & 7)]);
    }
    acc[0] = acc[1] = acc[2] = acc[3] = 0.f;

    for (int kt = 0; kt < ktCount; ++kt){
        __syncthreads();
#pragma unroll
        for (int p = 0; p < 8; ++p){
            int idx = tc + p*256;
            *reinterpret_cast<float4*>(&sWt[(idx >> 3)*36 + (idx & 7)*4]) = r[p];
        }
        __syncthreads();
        if (kt + 1 < ktCount){
#pragma unroll
            for (int p = 0; p < 8; ++p){
                int idx = tc + p*256;
                r[p] = __ldg(&Wp[(size_t)(idx >> 3)*64 + (ktStart+kt+1)*8 + (idx & 7)]);
            }
        }
        int kb = (ktStart + kt)*32;
#pragma unroll
        for (int kk4 = 0; kk4 < 8; ++kk4){
            float4 a0 = *(const float4*)&sA[0][kb + kk4*4];
            float4 a1 = *(const float4*)&sA[1][kb + kk4*4];
            float4 a2 = *(const float4*)&sA[2][kb + kk4*4];
            float4 a3 = *(const float4*)&sA[3][kb + kk4*4];
            float4 wv = *(const float4*)&sWt[tc*36 + kk4*4];
            acc[0] += a0.x*wv.x + a0.y*wv.y + a0.z*wv.z + a0.w*wv.w;
            acc[1] += a1.x*wv.x + a1.y*wv.y + a1.z*wv.z + a1.w*wv.w;
            acc[2] += a2.x*wv.x + a2.y*wv.y + a2.z*wv.z + a2.w*wv.w;
            acc[3] += a3.x*wv.x + a3.y*wv.y + a3.z*wv.z + a3.w*wv.w;
        }
    }
}

// ============ PRE, 512 threads: LN -> q (split-K gemm_tiles) -> qW (split-K stream) ==
__global__ __launch_bounds__(512) void pre_kernel(
        const float* __restrict__ slots,
        const float* __restrict__ lng, const float* __restrict__ lnb,
        const float* __restrict__ Wq,  const float* __restrict__ bq,
        const float* __restrict__ Wk,
        float* __restrict__ qW)
{
    extern __shared__ float dsm[];
    float (*s_ln)[DD] = (float(*)[DD])(dsm);            // 1024
    float (*s_q )[DD] = (float(*)[DD])(dsm + 1024);     // 1024
    float (*sPar)[DD] = (float(*)[DD])(dsm + 2048);     // 1024
    float* sWtA       = dsm + 3072;                     // 9216
    float* sWtB       = dsm + 12288;                    // 9216

    int r0 = blockIdx.x * 4;
    int t  = threadIdx.x;
    int tc = t & 255, grp = t >> 8;
    float* myWt = grp ? sWtB : sWtA;

    float v[4] = {0.f, 0.f, 0.f, 0.f};
    if (grp == 0){
#pragma unroll
        for (int r = 0; r < 4; ++r) v[r] = slots[(size_t)(r0+r)*DD + tc];
    }
    float o[4];
    block_ln4(v, o, lng, lnb, t);
    if (grp == 0){
#pragma unroll
        for (int r = 0; r < 4; ++r) s_ln[r][tc] = o[r];
    }
    // (leading sync inside gemm_tiles orders s_ln writes)

    // q = LN @ Wq^T + bq (split-K)
    float acc[4];
    gemm_tiles(s_ln, Wq, myWt, acc, tc, grp*4, 4);
    if (grp == 1){
#pragma unroll
        for (int r = 0; r < 4; ++r) sPar[r][tc] = acc[r];
    }
    __syncthreads();
    if (grp == 0){
        float bb = __ldg(&bq[tc]);
#pragma unroll
        for (int r = 0; r < 4; ++r) s_q[r][tc] = acc[r] + sPar[r][tc] + bb;
    }
    __syncthreads();

    // qW[r][e=tc] = (s_q[r] @ Wk[:,e]) / 16 (split-K column stream)
    {
        float c0=0.f, c1=0.f, c2=0.f, c3=0.f;
        int d0 = grp*128;
#pragma unroll 8
        for (int d = d0; d < d0 + 128; ++d){
            float wv = __ldg(&Wk[(size_t)d*IND + tc]);
            c0 += s_q[0][d]*wv; c1 += s_q[1][d]*wv;
            c2 += s_q[2][d]*wv; c3 += s_q[3][d]*wv;
        }
        if (grp == 1){
            sPar[0][tc] = c0; sPar[1][tc] = c1;
            sPar[2][tc] = c2; sPar[3][tc] = c3;
        }
        __syncthreads();
        if (grp == 0){
            qW[(size_t)(r0+0)*IND + tc] = (c0 + sPar[0][tc]) * 0.0625f;
            qW[(size_t)(r0+1)*IND + tc] = (c1 + sPar[1][tc]) * 0.0625f;
            qW[(size_t)(r0+2)*IND + tc] = (c2 + sPar[2][tc]) * 0.0625f;
            qW[(size_t)(r0+3)*IND + tc] = (c3 + sPar[3][tc]) * 0.0625f;
        }
    }
}

// ============ FLASH attention, TN=32 tiles, 2 blocks/SM, hoisted swizzle math ========
__global__ __launch_bounds__(512, 2) void attn_kernel(
        const float* __restrict__ qW,
        const float* __restrict__ inputs,
        float* __restrict__ upart,
        float* __restrict__ mbuf,
        float* __restrict__ lbuf)
{
    extern __shared__ float dsm[];
    float* Xs  = dsm;                  // 2 * 8192 floats (64 KB)
    float* qT  = dsm + 16384;          // [k][s] 2048
    float* lgp = qT  + 2048;           // [ks][s][n] 16*8*32 = 4096
    float* atT = lgp + 4096;           // [n][12] 384
    float* scs = atT + 384;            // 8

    int b = blockIdx.x, g = blockIdx.y;
    int t = threadIdx.x, w = t >> 5, l = t & 31;

    // stage qT
#pragma unroll
    for (int p = 0; p < 4; ++p){
        int idx = t + p*512;
        qT[(idx & 255)*8 + (idx >> 8)] = qW[(size_t)b*2048 + idx];
    }

    const float* src0 = inputs + ((size_t)b*NN + g*(NTILE*TN))*IND;
#define PREFETCH(j, buf) do {                                                   \
        const float* _s = src0 + (size_t)(j)*TN*IND;                            \
        float* _d = Xs + (buf)*8192;                                            \
        _Pragma("unroll")                                                       \
        for (int p = 0; p < 4; ++p){                                            \
            int idx = t + p*512;                                                \
            int n = idx >> 6, k4 = idx & 63;                                    \
            uint32_t sa = (uint32_t)__cvta_generic_to_shared(                   \
                              &_d[(n*64 + (k4 ^ (n & 7)))*4]);                  \
            asm volatile("cp.async.cg.shared.global [%0], [%1], 16;"            \
                         :: "r"(sa), "l"(_s + (size_t)n*IND + k4*4) : "memory");\
        }                                                                       \
        asm volatile("cp.async.commit_group;" ::: "memory");                    \
    } while(0)

    PREFETCH(0, 0);

    float m_run = -3.4e38f, lpart = 0.f;
    float uacc[4] = {};
    const int sh = (t >= 256) ? 4 : 0;     // phase3 slot-half
    const int e  = t & 255;
    const int e4 = e >> 2, eo = e & 3;
    const int ks = t >> 5;                 // phase1 k-slice (= warp id)
    const int pn = t & 31;                 // phase1 n (= lane)

    // ---- hoisted swizzle address math ----
    const int c  = pn & 7;
    const int p1base = pn*256 + ((ks*4) ^ (c & 4))*4;
    int a1[4];
#pragma unroll
    for (int i = 0; i < 4; ++i) a1[i] = p1base + (i ^ (c & 3))*4;
    int off3[8];
#pragma unroll
    for (int cc = 0; cc < 8; ++cc) off3[cc] = (e4 ^ cc)*4 + eo;

    for (int j = 0; j < NTILE; ++j){
        int buf = j & 1;
        asm volatile("cp.async.wait_group 0;" ::: "memory");
        __syncthreads();                                   // S1: tile ready, prior reads done
        if (j + 1 < NTILE) PREFETCH(j + 1, buf ^ 1);
        const float* Xb = Xs + buf*8192;

        // ---- phase 1: logits partials; warp = k-slice (16 k), lane = n ----
        {
            float acc[8] = {};
#pragma unroll
            for (int i = 0; i < 4; ++i){
                float4 x4 = *(const float4*)&Xb[a1[i]];
                int k = (ks*4 + i)*4;
                float xv[4] = {x4.x, x4.y, x4.z, x4.w};
#pragma unroll
                for (int d = 0; d < 4; ++d){
                    float4 qa = *(const float4*)&qT[(k+d)*8];
                    float4 qb = *(const float4*)&qT[(k+d)*8 + 4];
                    acc[0] += xv[d]*qa.x; acc[1] += xv[d]*qa.y;
                    acc[2] += xv[d]*qa.z; acc[3] += xv[d]*qa.w;
                    acc[4] += xv[d]*qb.x; acc[5] += xv[d]*qb.y;
                    acc[6] += xv[d]*qb.z; acc[7] += xv[d]*qb.w;
                }
            }
#pragma unroll
            for (int s = 0; s < 8; ++s) lgp[ks*256 + s*32 + pn] = acc[s];
        }
        __syncthreads();                                   // S2: lgp ready

        // ---- phase 2: online softmax; warp w<8 owns slot w, lane = key ----
        if (w < 8){
            float lg = 0.f;
#pragma unroll
            for (int kq = 0; kq < 16; ++kq) lg += lgp[kq*256 + w*32 + l];
            float mv = warpMax(lg);
            float m_new = fmaxf(m_run, mv);
            float ev = __expf(lg - m_new);
            atT[l*12 + w] = ev;
            float sc = __expf(m_run - m_new);
            lpart = lpart*sc + ev;
            m_run = m_new;
            if (l == 0) scs[w] = sc;
        }
        __syncthreads();                                   // S3: atT/scs ready

        // ---- phase 3: U accumulation; halves own slots sh..sh+3, col e ----
        {
            float4 sv = *(const float4*)&scs[sh];
            uacc[0] *= sv.x; uacc[1] *= sv.y; uacc[2] *= sv.z; uacc[3] *= sv.w;
            for (int n8 = 0; n8 < TN; n8 += 8){
#pragma unroll
                for (int cc = 0; cc < 8; ++cc){
                    int n = n8 + cc;
                    float x = Xb[n*256 + off3[cc]];
                    float4 a = *(const float4*)&atT[n*12 + sh];
                    uacc[0] += a.x*x; uacc[1] += a.y*x;
                    uacc[2] += a.z*x; uacc[3] += a.w*x;
                }
            }
        }
    }
#undef PREFETCH

#pragma unroll
    for (int i = 0; i < 4; ++i)
        upart[((size_t)g*ROWS + b*SS + sh + i)*IND + e] = uacc[i];
    if (w < 8){
        float l_run = warpSum(lpart);
        if (l == 0){
            int row = b*SS + w;
            mbuf[(size_t)g*ROWS + row] = m_run;
            lbuf[(size_t)g*ROWS + row] = l_run;
        }
    }
}

// ============ POST, 512 threads: split-K GEMMs + concurrent GRU gates ============
__global__ __launch_bounds__(512) void post_kernel(
        const float* __restrict__ upart,
        const float* __restrict__ mbuf, const float* __restrict__ lbuf,
        const float* __restrict__ Wv,   const float* __restrict__ bv,
        const float* __restrict__ W_ih, const float* __restrict__ b_ih,
        const float* __restrict__ W_hh, const float* __restrict__ b_hh,
        const float* __restrict__ lng,  const float* __restrict__ lnb,
        const float* __restrict__ W1,   const float* __restrict__ b1,
        const float* __restrict__ W2,   const float* __restrict__ b2,
        const float* __restrict__ slots_in,
        float* __restrict__ dst)
{
    extern __shared__ float dsm[];
    float (*sBufA)[DD] = (float(*)[DD])(dsm);           // 1024  U / sln
    float (*sprev)[DD] = (float(*)[DD])(dsm + 1024);    // 1024
    float (*sBufB)[DD] = (float(*)[DD])(dsm + 2048);    // 1024  upd / hid
    float* sGh         = dsm + 3072;                    // 3072  gh[3][4][256]
    float (*sPar)[DD]  = (float(*)[DD])(dsm + 6144);    // 1024  split-k partials
    float* sWtA        = dsm + 7168;                    // 9216
    float* sWtB        = dsm + 16384;                   // 9216

    __shared__ float ssc[4][17];
    __shared__ float sinv[4];

    int r0 = blockIdx.x * 4;
    int t  = threadIdx.x;
    int tc = t & 255, grp = t >> 8;
    int w  = t >> 5, l = t & 31;
    float* myWt = grp ? sWtB : sWtA;

    // 1. per-row combine scales over NG=16 groups (warps 0-3, lanes 0-15)
    if (w < 4){
        int row = r0 + w;
        float mv = (l < NG) ? __ldg(&mbuf[(size_t)l*ROWS + row]) : -3.4e38f;
        float mm = mv;
        mm = fmaxf(mm, __shfl_xor_sync(0xffffffffu, mm, 1));
        mm = fmaxf(mm, __shfl_xor_sync(0xffffffffu, mm, 2));
        mm = fmaxf(mm, __shfl_xor_sync(0xffffffffu, mm, 4));
        mm = fmaxf(mm, __shfl_xor_sync(0xffffffffu, mm, 8));
        float e  = (l < NG) ? __expf(mv - mm) : 0.f;
        float lv = (l < NG) ? __ldg(&lbuf[(size_t)l*ROWS + row]) * e : 0.f;
        lv += __shfl_xor_sync(0xffffffffu, lv, 1);
        lv += __shfl_xor_sync(0xffffffffu, lv, 2);
        lv += __shfl_xor_sync(0xffffffffu, lv, 4);
        lv += __shfl_xor_sync(0xffffffffu, lv, 8);
        if (l < NG) ssc[w][l] = e;
        if (l == 0) sinv[w] = 1.f / lv;
    }
    __syncthreads();

    // 2. U = (sum_g Ubar_g*sc_g)*inv ; load slots_prev (each thread 2 rows)
#pragma unroll
    for (int rr = 0; rr < 2; ++rr){
        int r = grp*2 + rr, row = r0 + r;
        float a = 0.f;
#pragma unroll
        for (int ch = 0; ch < NG; ++ch)
            a += __ldg(&upart[((size_t)ch*ROWS + row)*IND + tc]) * ssc[r][ch];
        sBufA[r][tc] = a * sinv[r];
        sprev[r][tc] = slots_in[(size_t)row*DD + tc];
    }
    // (first barrier inside gemm_tiles orders these writes)

    // 3. upd = U @ Wv^T + bv  (split-K)
    float acc[4];
    gemm_tiles(sBufA, Wv, myWt, acc, tc, grp*4, 4);
    if (grp == 1){
#pragma unroll
        for (int r = 0; r < 4; ++r) sPar[r][tc] = acc[r];
    }
    __syncthreads();
    if (grp == 0){
        float bb = __ldg(&bv[tc]);
#pragma unroll
        for (int r = 0; r < 4; ++r) sBufB[r][tc] = acc[r] + sPar[r][tc] + bb;
    }

    // 4. GRU gates concurrently: grp0 -> gi (W_ih on upd), grp1 -> gh (W_hh on prev)
    float gi[3][4];
#pragma unroll
    for (int j = 0; j < 3; ++j){
        const float* Wg = grp ? (W_hh + (size_t)j*DD*DD) : (W_ih + (size_t)j*DD*DD);
        const float (*Ag)[DD] = grp ? sprev : sBufB;
        gemm_tiles(Ag, Wg, myWt, acc, tc, 0, 8);
        if (grp == 0){
            float bb = __ldg(&b_ih[tc + j*256]);
#pragma unroll
            for (int r = 0; r < 4; ++r) gi[j][r] = acc[r] + bb;
        } else {
            float bb = __ldg(&b_hh[tc + j*256]);
#pragma unroll
            for (int r = 0; r < 4; ++r) sGh[(j*4 + r)*256 + tc] = acc[r] + bb;
        }
    }
    __syncthreads();

    // 5. GRU cell + residual (grp0)
    float vnew[4] = {0.f, 0.f, 0.f, 0.f};
    if (grp == 0){
#pragma unroll
        for (int r = 0; r < 4; ++r){
            float hr = sGh[(0*4 + r)*256 + tc];
            float hz = sGh[(1*4 + r)*256 + tc];
            float hn = sGh[(2*4 + r)*256 + tc];
            float rr = 1.f / (1.f + expf(-(gi[0][r] + hr)));
            float zz = 1.f / (1.f + expf(-(gi[1][r] + hz)));
            float nn = tanhf(gi[2][r] + rr*hn);
            float h  = sprev[r][tc];
            vnew[r]  = h + (1.f - zz)*nn + zz*h;
        }
    }

    // 6. LN(vnew) -> sBufA (grp0 data; all threads pass barriers)
    float lnv[4];
    block_ln4(vnew, lnv, lng, lnb, t);
    if (grp == 0){
#pragma unroll
        for (int r = 0; r < 4; ++r) sBufA[r][tc] = lnv[r];
    }

    // 7. hidden = relu(sln @ W1^T + b1) -> sBufB (split-K)
    gemm_tiles(sBufA, W1, myWt, acc, tc, grp*4, 4);
    if (grp == 1){
#pragma unroll
        for (int r = 0; r < 4; ++r) sPar[r][tc] = acc[r];
    }
    __syncthreads();
    if (grp == 0){
        float bb = __ldg(&b1[tc]);
#pragma unroll
        for (int r = 0; r < 4; ++r) sBufB[r][tc] = fmaxf(acc[r] + sPar[r][tc] + bb, 0.f);
    }

    // 8. out = vnew + hid @ W2^T + b2 (split-K)
    gemm_tiles(sBufB, W2, myWt, acc, tc, grp*4, 4);
    if (grp == 1){
#pragma unroll
        for (int r = 0; r < 4; ++r) sPar[r][tc] = acc[r];
    }
    __syncthreads();
    if (grp == 0){
        float bb = __ldg(&b2[tc]);
#pragma unroll
        for (int r = 0; r < 4; ++r)
            dst[(size_t)(r0+r)*DD + tc] = vnew[r] + acc[r] + sPar[r][tc] + bb;
    }
}

// ------------------------- host launcher -------------------------
extern "C" void kernel_launch(void* const* d_in, const int* in_sizes, int n_in,
                              void* d_out, int out_size)
{
    const float* inputs = (const float*)d_in[0];
    const float* noise  = (const float*)d_in[1];
    const float* s_mu   = (const float*)d_in[2];
    const float* s_sig  = (const float*)d_in[3];
    const float* Wq = (const float*)d_in[4];  const float* bq = (const float*)d_in[5];
    const float* Wk = (const float*)d_in[6];  /* bk = d_in[7] : dead (softmax shift-invariance) */
    const float* Wv = (const float*)d_in[8];  const float* bv = (const float*)d_in[9];
    const float* W_ih = (const float*)d_in[10]; const float* b_ih = (const float*)d_in[11];
    const float* W_hh = (const float*)d_in[12]; const float* b_hh = (const float*)d_in[13];
    const float* W1 = (const float*)d_in[14]; const float* b1 = (const float*)d_in[15];
    const float* W2 = (const float*)d_in[16]; const float* b2 = (const float*)d_in[17];
    const float* lnsg = (const float*)d_in[18]; const float* lnsb = (const float*)d_in[19];
    const float* lnmg = (const float*)d_in[20]; const float* lnmb = (const float*)d_in[21];
    float* out = (float*)d_out;
    (void)in_sizes; (void)n_in; (void)out_size;

    float *slots, *qW, *upart, *mbuf, *lbuf;
    cudaGetSymbolAddress((void**)&slots, g_slots);
    cudaGetSymbolAddress((void**)&qW,    g_qW);
    cudaGetSymbolAddress((void**)&upart, g_upart);
    cudaGetSymbolAddress((void**)&mbuf,  g_m);
    cudaGetSymbolAddress((void**)&lbuf,  g_l);

    const int ATTN_SMEM = (16384 + 2048 + 4096 + 384 + 8) * 4;   // 91,680 B -> 2 blocks/SM
    const int POST_SMEM = (7168 + 9216*2) * 4;                   // 102,400 B
    const int PRE_SMEM  = (3072 + 9216*2) * 4;                   //  86,016 B
    static int s_init = 0;
    if (!s_init){
        cudaFuncSetAttribute(attn_kernel, cudaFuncAttributeMaxDynamicSharedMemorySize, ATTN_SMEM);
        cudaFuncSetAttribute(post_kernel, cudaFuncAttributeMaxDynamicSharedMemorySize, POST_SMEM);
        cudaFuncSetAttribute(pre_kernel,  cudaFuncAttributeMaxDynamicSharedMemorySize, PRE_SMEM);
        s_init = 1;
    }

    dim3 gBN(BB, NG);

    init_slots_kernel<<<ROWS, 256>>>(noise, s_mu, s_sig, slots);

    for (int it = 0; it < 3; ++it){
        pre_kernel<<<ROWS/4, 512, PRE_SMEM>>>(slots, lnsg, lnsb, Wq, bq, Wk, qW);
        attn_kernel<<<gBN, 512, ATTN_SMEM>>>(qW, inputs, upart, mbuf, lbuf);
        float* dst = (it == 2) ? out : slots;
        post_kernel<<<ROWS/4, 512, POST_SMEM>>>(upart, mbuf, lbuf, Wv, bv, W_ih, b_ih, W_hh, b_hh,
                                                lnmg, lnmb, W1, b1, W2, b2, slots, dst);
    }
}